// round 1
// baseline (speedup 1.0000x reference)
#include <cuda_runtime.h>
#include <cuda_bf16.h>
#include <math.h>

// ---------------- problem constants ----------------
#define N_USER   100000
#define N_ITEM   50000
#define NTOT     (N_USER + N_ITEM)     // 150000
#define EMB      64
#define FEAT     384
#define NNZ      2400000
#define N_PROMPT 8
#define N_LAYERS 4
#define EPS_     1e-8f

#define SCAN_BLK 256
#define NB_SCAN  ((NTOT + SCAN_BLK - 1) / SCAN_BLK)   // 586

// ---------------- device scratch (static, no runtime alloc) ----------------
__device__ float  g_ego [NTOT * EMB];     // layer-0 embeddings (= x0)
__device__ float  g_xA  [NTOT * EMB];     // ping
__device__ float  g_xB  [NTOT * EMB];     // pong
__device__ float  g_norm[NTOT];           // ||ego|| per row
__device__ float  g_prompt[EMB];          // sum of prompt embeddings
__device__ int    g_deg   [NTOT];
__device__ int    g_rowptr[NTOT + 1];
__device__ int    g_cursor[NTOT];
__device__ int    g_bsums [1024];
__device__ int    g_boffs [1024];
__device__ int2   g_edges [NNZ];          // {col, float-bits(val)} packed per edge

// ---------------- 1) prompt sum ----------------
__global__ void k_prompt(const float* __restrict__ pe) {
    int t = threadIdx.x;              // 64 threads
    float s = 0.f;
    #pragma unroll
    for (int p = 0; p < N_PROMPT; ++p) s += pe[p * EMB + t];
    g_prompt[t] = s;
}

// ---------------- 2) user ego = user_fea + prompt ----------------
__global__ void k_user_ego(const float* __restrict__ uf) {
    int i = blockIdx.x * blockDim.x + threadIdx.x;
    if (i < N_USER * EMB)
        g_ego[i] = uf[i] + g_prompt[i & (EMB - 1)];
}

// ---------------- 3) item GEMM + tanh -> ego ----------------
// block: 256 thr, tile 64 rows x 64 cols, 16 outputs/thread, K-chunks of 32
__global__ __launch_bounds__(256) void k_gemm(const float* __restrict__ A,   // [N_ITEM, FEAT]
                                              const float* __restrict__ B,   // [FEAT, EMB]
                                              const float* __restrict__ bias)
{
    __shared__ float As[64][32];   // [row][k]   (row = 128B -> LDS.128 ok)
    __shared__ float Bs[32][64];   // [k][col]

    const int t     = threadIdx.x;
    const int c     = t & 63;            // output column 0..63
    const int rq    = t >> 6;            // row quadrant 0..3
    const int row0  = blockIdx.x * 64;

    float acc[16];
    #pragma unroll
    for (int j = 0; j < 16; ++j) acc[j] = 0.f;

    for (int k0 = 0; k0 < FEAT; k0 += 32) {
        // load A tile (guard tail rows)
        #pragma unroll
        for (int i = 0; i < 8; ++i) {
            int lin = i * 256 + t;
            int r = lin >> 5, k = lin & 31;
            int gr = row0 + r;
            As[r][k] = (gr < N_ITEM) ? A[gr * FEAT + k0 + k] : 0.f;
        }
        // load B tile
        #pragma unroll
        for (int i = 0; i < 8; ++i) {
            int lin = i * 256 + t;
            int k = lin >> 6, cc = lin & 63;
            Bs[k][cc] = B[(k0 + k) * EMB + cc];
        }
        __syncthreads();

        float bv[32];
        #pragma unroll
        for (int kk = 0; kk < 32; ++kk) bv[kk] = Bs[kk][c];

        #pragma unroll
        for (int j = 0; j < 16; ++j) {
            const float4* ar = (const float4*)&As[rq * 16 + j][0];
            #pragma unroll
            for (int q = 0; q < 8; ++q) {
                float4 a = ar[q];
                acc[j] += a.x * bv[4*q] + a.y * bv[4*q+1]
                        + a.z * bv[4*q+2] + a.w * bv[4*q+3];
            }
        }
        __syncthreads();
    }

    float bb = bias[c];
    #pragma unroll
    for (int j = 0; j < 16; ++j) {
        int row = row0 + rq * 16 + j;
        if (row < N_ITEM)
            g_ego[(N_USER + row) * EMB + c] = tanhf(acc[j] + bb);
    }
}

// ---------------- 4) per-row norm + init out = ego ----------------
__global__ void k_norm_init(float* __restrict__ out) {
    int gw   = (blockIdx.x * blockDim.x + threadIdx.x) >> 5;
    int lane = threadIdx.x & 31;
    if (gw >= NTOT) return;
    const float2* e2 = (const float2*)g_ego;
    float2 v = e2[gw * 32 + lane];
    ((float2*)out)[gw * 32 + lane] = v;
    float s = v.x * v.x + v.y * v.y;
    #pragma unroll
    for (int o = 16; o; o >>= 1) s += __shfl_xor_sync(0xffffffffu, s, o);
    if (lane == 0) g_norm[gw] = sqrtf(s);
}

// ---------------- CSR build ----------------
__global__ void k_zero_deg() {
    int i = blockIdx.x * blockDim.x + threadIdx.x;
    if (i < NTOT) g_deg[i] = 0;
}
__global__ void k_hist(const int* __restrict__ rows) {
    int e = blockIdx.x * blockDim.x + threadIdx.x;
    if (e < NNZ) atomicAdd(&g_deg[rows[e]], 1);
}
__global__ void k_scan1() {
    __shared__ int sh[SCAN_BLK];
    int t = threadIdx.x;
    int idx = blockIdx.x * SCAN_BLK + t;
    int v = (idx < NTOT) ? g_deg[idx] : 0;
    sh[t] = v;
    __syncthreads();
    for (int off = 1; off < SCAN_BLK; off <<= 1) {
        int add = (t >= off) ? sh[t - off] : 0;
        __syncthreads();
        sh[t] += add;
        __syncthreads();
    }
    if (idx < NTOT) g_rowptr[idx] = sh[t] - v;      // exclusive
    if (t == SCAN_BLK - 1) g_bsums[blockIdx.x] = sh[t];
}
__global__ void k_scan2() {                          // 1 block, 1024 threads
    __shared__ int sh[1024];
    int t = threadIdx.x;
    int v = (t < NB_SCAN) ? g_bsums[t] : 0;
    sh[t] = v;
    __syncthreads();
    for (int off = 1; off < 1024; off <<= 1) {
        int add = (t >= off) ? sh[t - off] : 0;
        __syncthreads();
        sh[t] += add;
        __syncthreads();
    }
    if (t < NB_SCAN) g_boffs[t] = sh[t] - v;         // exclusive
    if (t == 1023)   g_rowptr[NTOT] = sh[1023];      // == NNZ
}
__global__ void k_scan3() {
    int i = blockIdx.x * blockDim.x + threadIdx.x;
    if (i < NTOT) {
        int r = g_rowptr[i] + g_boffs[i >> 8];
        g_rowptr[i] = r;
        g_cursor[i] = r;
    }
}
__global__ void k_scatter(const int* __restrict__ rows,
                          const int* __restrict__ cols,
                          const float* __restrict__ vals) {
    int e = blockIdx.x * blockDim.x + threadIdx.x;
    if (e < NNZ) {
        int p = atomicAdd(&g_cursor[rows[e]], 1);
        g_edges[p] = make_int2(cols[e], __float_as_int(vals[e]));
    }
}

// ---------------- fused propagate layer (warp per row) ----------------
// x_new = SpMM(adj, x); w = cos(x_new, ego); x_new *= w; out += x_new
__global__ __launch_bounds__(256) void k_prop(const float2* __restrict__ x,
                                              float2* __restrict__ xn,
                                              float2* __restrict__ out)
{
    int gw   = (blockIdx.x * blockDim.x + threadIdx.x) >> 5;
    int lane = threadIdx.x & 31;
    if (gw >= NTOT) return;

    int beg = g_rowptr[gw];
    int end = g_rowptr[gw + 1];

    float2 acc = make_float2(0.f, 0.f);
    for (int e = beg; e < end; ++e) {
        int2  cv = g_edges[e];                 // broadcast (same addr warp-wide)
        float v  = __int_as_float(cv.y);
        float2 xv = x[cv.x * 32 + lane];       // coalesced 256B row gather
        acc.x += v * xv.x;
        acc.y += v * xv.y;
    }

    float2 eg = ((const float2*)g_ego)[gw * 32 + lane];
    float dot = acc.x * eg.x + acc.y * eg.y;
    float nrm = acc.x * acc.x + acc.y * acc.y;
    #pragma unroll
    for (int o = 16; o; o >>= 1) {
        dot += __shfl_xor_sync(0xffffffffu, dot, o);
        nrm += __shfl_xor_sync(0xffffffffu, nrm, o);
    }
    float w = dot / fmaxf(sqrtf(nrm) * g_norm[gw], EPS_);

    float2 r = make_float2(w * acc.x, w * acc.y);
    xn[gw * 32 + lane] = r;
    float2 o2 = out[gw * 32 + lane];
    o2.x += r.x; o2.y += r.y;
    out[gw * 32 + lane] = o2;
}

// ---------------- launch ----------------
extern "C" void kernel_launch(void* const* d_in, const int* in_sizes, int n_in,
                              void* d_out, int out_size)
{
    const float* user_fea = (const float*)d_in[0];
    const float* item_fea = (const float*)d_in[1];
    const float* prompt   = (const float*)d_in[2];
    const float* mlp_w    = (const float*)d_in[3];
    const float* mlp_b    = (const float*)d_in[4];
    const int*   adj_rows = (const int*)  d_in[5];
    const int*   adj_cols = (const int*)  d_in[6];
    const float* adj_vals = (const float*)d_in[7];
    float* out = (float*)d_out;

    // --- embeddings ---
    k_prompt  <<<1, EMB>>>(prompt);
    k_user_ego<<<(N_USER * EMB + 255) / 256, 256>>>(user_fea);
    k_gemm    <<<(N_ITEM + 63) / 64, 256>>>(item_fea, mlp_w, mlp_b);
    k_norm_init<<<(NTOT * 32 + 255) / 256, 256>>>(out);

    // --- CSR build ---
    k_zero_deg<<<(NTOT + 255) / 256, 256>>>();
    k_hist    <<<(NNZ + 255) / 256, 256>>>(adj_rows);
    k_scan1   <<<NB_SCAN, SCAN_BLK>>>();
    k_scan2   <<<1, 1024>>>();
    k_scan3   <<<(NTOT + 255) / 256, 256>>>();
    k_scatter <<<(NNZ + 255) / 256, 256>>>(adj_rows, adj_cols, adj_vals);

    // --- 4 propagation layers (ping-pong; layer 0 reads ego) ---
    float2* ego2 = nullptr; float2* xA2 = nullptr; float2* xB2 = nullptr;
    cudaGetSymbolAddress((void**)&ego2, g_ego);
    cudaGetSymbolAddress((void**)&xA2,  g_xA);
    cudaGetSymbolAddress((void**)&xB2,  g_xB);
    float2* out2 = (float2*)out;

    int pblocks = (NTOT * 32 + 255) / 256;
    k_prop<<<pblocks, 256>>>(ego2, xA2, out2);
    k_prop<<<pblocks, 256>>>(xA2,  xB2, out2);
    k_prop<<<pblocks, 256>>>(xB2,  xA2, out2);
    k_prop<<<pblocks, 256>>>(xA2,  xB2, out2);
}